// round 4
// baseline (speedup 1.0000x reference)
#include <cuda_runtime.h>
#include <math.h>

#define Nn 50000
#define En 800000
#define Cc 16
#define Mm 32
#define Gg 8
#define CG (Cc*Gg)          // 128

// ---- scratch (module-static, allowed) ----
__device__ float g_smB0[Cc*Mm*Gg];   // softmax(B0, axis=M)
__device__ float g_smPi[Cc*Gg];      // softmax(Pi, axis=C)
__device__ float g_smB1[Cc*Mm*Gg];   // softmax(B1, axis=M)
__device__ float g_smQ[Cc*Cc*Gg];    // softmax(Q, axis=0 (i))
__device__ float g_post0[(size_t)Nn*CG];
__device__ float g_aggr[(size_t)Nn*CG];
__device__ float g_cnt[Nn];

// ---------------------------------------------------------------------------
// 1) All four softmaxes in one small block (128 threads).
//    thread t: g = t&7, r = t>>3 (r = c for B0/B1 rows, r = l for Q columns)
// ---------------------------------------------------------------------------
__global__ void k_softmax(const float* __restrict__ B0, const float* __restrict__ Pi,
                          const float* __restrict__ B1, const float* __restrict__ Q)
{
    int t = threadIdx.x;
    if (t >= 128) return;
    int g = t & 7;
    int r = t >> 3;

    // B0 row (c=r, g): softmax over m
    {
        float mx = -1e30f;
        #pragma unroll
        for (int m = 0; m < Mm; m++) mx = fmaxf(mx, B0[r*Mm*Gg + m*Gg + g]);
        float e[Mm]; float s = 0.f;
        #pragma unroll
        for (int m = 0; m < Mm; m++) { e[m] = expf(B0[r*Mm*Gg + m*Gg + g] - mx); s += e[m]; }
        float inv = 1.f / s;
        #pragma unroll
        for (int m = 0; m < Mm; m++) g_smB0[r*Mm*Gg + m*Gg + g] = e[m] * inv;
    }
    // B1 row (c=r, g)
    {
        float mx = -1e30f;
        #pragma unroll
        for (int m = 0; m < Mm; m++) mx = fmaxf(mx, B1[r*Mm*Gg + m*Gg + g]);
        float e[Mm]; float s = 0.f;
        #pragma unroll
        for (int m = 0; m < Mm; m++) { e[m] = expf(B1[r*Mm*Gg + m*Gg + g] - mx); s += e[m]; }
        float inv = 1.f / s;
        #pragma unroll
        for (int m = 0; m < Mm; m++) g_smB1[r*Mm*Gg + m*Gg + g] = e[m] * inv;
    }
    // Q column (l=r, g): softmax over i (dim 0)
    {
        float mx = -1e30f;
        #pragma unroll
        for (int i = 0; i < Cc; i++) mx = fmaxf(mx, Q[i*Cc*Gg + r*Gg + g]);
        float e[Cc]; float s = 0.f;
        #pragma unroll
        for (int i = 0; i < Cc; i++) { e[i] = expf(Q[i*Cc*Gg + r*Gg + g] - mx); s += e[i]; }
        float inv = 1.f / s;
        #pragma unroll
        for (int i = 0; i < Cc; i++) g_smQ[i*Cc*Gg + r*Gg + g] = e[i] * inv;
    }
    // Pi column g (threads 0..7): softmax over c
    if (t < Gg) {
        float mx = -1e30f;
        #pragma unroll
        for (int c = 0; c < Cc; c++) mx = fmaxf(mx, Pi[c*Gg + t]);
        float e[Cc]; float s = 0.f;
        #pragma unroll
        for (int c = 0; c < Cc; c++) { e[c] = expf(Pi[c*Gg + t] - mx); s += e[c]; }
        float inv = 1.f / s;
        #pragma unroll
        for (int c = 0; c < Cc; c++) g_smPi[c*Gg + t] = e[c] * inv;
    }
}

// ---------------------------------------------------------------------------
// 2) Layer 0: per (n,g) compute post0 and ll0.
// ---------------------------------------------------------------------------
__global__ void k_layer0(const int* __restrict__ x, float* __restrict__ out)
{
    int idx = blockIdx.x * blockDim.x + threadIdx.x;
    if (idx >= Nn * Gg) return;
    int n = idx >> 3, g = idx & 7;
    int xm = x[n];
    float u[Cc]; float s = 0.f;
    #pragma unroll
    for (int c = 0; c < Cc; c++) {
        u[c] = g_smPi[c*Gg + g] * g_smB0[c*Mm*Gg + xm*Gg + g];
        s += u[c];
    }
    out[(size_t)n * (2*Gg) + g] = logf(s);   // ll layer 0
    float inv = 1.f / s;
    size_t base = (size_t)n * CG + g;
    #pragma unroll
    for (int c = 0; c < Cc; c++) g_post0[base + c*Gg] = u[c] * inv;
}

// ---------------------------------------------------------------------------
// 3) Zero the accumulators (must run every launch — graph replay).
//    25000 blocks * 256 = exactly N*C*G threads; first Nn also zero cnt.
// ---------------------------------------------------------------------------
__global__ void k_zero()
{
    int i = blockIdx.x * blockDim.x + threadIdx.x;
    g_aggr[i] = 0.f;
    if (i < Nn) g_cnt[i] = 0.f;
}

// ---------------------------------------------------------------------------
// 4a) Degree count: one thread per edge.
// ---------------------------------------------------------------------------
__global__ void k_cnt(const int* __restrict__ ei)
{
    int e = blockIdx.x * blockDim.x + threadIdx.x;
    if (e >= En) return;
    atomicAdd(&g_cnt[ei[e]], 1.0f);
}

// ---------------------------------------------------------------------------
// 4b) Scatter-add: thread per (edge, j), j in [0,128). 102.4M threads.
//     aggr[src] += post0[dst]
// ---------------------------------------------------------------------------
__global__ void k_scatter(const int* __restrict__ ei)
{
    int gid = blockIdx.x * blockDim.x + threadIdx.x;   // < E*128 = 102.4M < 2^31
    int e = gid >> 7;
    int j = gid & 127;
    int src = ei[e];
    int dst = ei[En + e];
    atomicAdd(&g_aggr[(size_t)src * CG + j], g_post0[(size_t)dst * CG + j]);
}

// ---------------------------------------------------------------------------
// 5) Layer 1: per (n,g).
//    post1[i] = B1[i,x,g] * (sum_l Q[i,l,g]*aggr[l]) / norm ; ll1 = log(norm)
// ---------------------------------------------------------------------------
__global__ void k_layer1(const int* __restrict__ x, float* __restrict__ out)
{
    int idx = blockIdx.x * blockDim.x + threadIdx.x;
    if (idx >= Nn * Gg) return;
    int n = idx >> 3, g = idx & 7;
    int xm = x[n];
    float inv_cnt = 1.f / fmaxf(g_cnt[n], 1.f);

    float a[Cc];
    size_t abase = (size_t)n * CG + g;
    #pragma unroll
    for (int l = 0; l < Cc; l++) a[l] = g_aggr[abase + l*Gg] * inv_cnt;

    float tv[Cc]; float norm = 0.f;
    #pragma unroll
    for (int i = 0; i < Cc; i++) {
        float s = 0.f;
        #pragma unroll
        for (int l = 0; l < Cc; l++) s += g_smQ[i*Cc*Gg + l*Gg + g] * a[l];
        float v = g_smB1[i*Mm*Gg + xm*Gg + g] * s;
        tv[i] = v;
        norm += v;
    }
    out[(size_t)n * (2*Gg) + Gg + g] = logf(norm);   // ll layer 1
    float invn = 1.f / norm;
    float* p1 = out + (size_t)Nn * 2 * Gg;
    size_t pbase = (size_t)n * CG + g;
    #pragma unroll
    for (int i = 0; i < Cc; i++) p1[pbase + i*Gg] = tv[i] * invn;
}

// ---------------------------------------------------------------------------
extern "C" void kernel_launch(void* const* d_in, const int* in_sizes, int n_in,
                              void* d_out, int out_size)
{
    const int*   x  = (const int*)  d_in[0];
    const int*   ei = (const int*)  d_in[1];   // [2, E]
    const float* B0 = (const float*)d_in[2];
    const float* Pi = (const float*)d_in[3];
    const float* B1 = (const float*)d_in[4];
    const float* Q  = (const float*)d_in[5];
    float* out = (float*)d_out;

    k_softmax<<<1, 128>>>(B0, Pi, B1, Q);
    k_zero<<<(Nn * CG) / 256, 256>>>();                 // 25000 blocks, exact
    k_layer0<<<(Nn * Gg + 255) / 256, 256>>>(x, out);
    k_cnt<<<(En + 255) / 256, 256>>>(ei);
    k_scatter<<<(En * 128) / 256, 256>>>(ei);           // 400000 blocks, exact
    k_layer1<<<(Nn * Gg + 255) / 256, 256>>>(x, out);
}

// round 5
// speedup vs baseline: 2.3379x; 2.3379x over previous
#include <cuda_runtime.h>
#include <math.h>

#define Nn 50000
#define En 800000
#define Cc 16
#define Mm 32
#define Gg 8
#define CG (Cc*Gg)          // 128

// ---- scratch (module-static, allowed) ----
__device__ float g_smB0[Cc*Mm*Gg];   // softmax(B0, axis=M)
__device__ float g_smPi[Cc*Gg];      // softmax(Pi, axis=C)
__device__ float g_smB1[Cc*Mm*Gg];   // softmax(B1, axis=M)
__device__ float g_smQ[Cc*Cc*Gg];    // softmax(Q, axis=0 (i))
__device__ float g_post0[(size_t)Nn*CG];
__device__ float g_aggr[(size_t)Nn*CG];
__device__ float g_cnt[Nn];

// ---------------------------------------------------------------------------
// 1) All four softmaxes in one small block (128 threads).
// ---------------------------------------------------------------------------
__global__ void k_softmax(const float* __restrict__ B0, const float* __restrict__ Pi,
                          const float* __restrict__ B1, const float* __restrict__ Q)
{
    int t = threadIdx.x;
    if (t >= 128) return;
    int g = t & 7;
    int r = t >> 3;

    // B0 row (c=r, g): softmax over m
    {
        float mx = -1e30f;
        #pragma unroll
        for (int m = 0; m < Mm; m++) mx = fmaxf(mx, B0[r*Mm*Gg + m*Gg + g]);
        float e[Mm]; float s = 0.f;
        #pragma unroll
        for (int m = 0; m < Mm; m++) { e[m] = expf(B0[r*Mm*Gg + m*Gg + g] - mx); s += e[m]; }
        float inv = 1.f / s;
        #pragma unroll
        for (int m = 0; m < Mm; m++) g_smB0[r*Mm*Gg + m*Gg + g] = e[m] * inv;
    }
    // B1 row (c=r, g)
    {
        float mx = -1e30f;
        #pragma unroll
        for (int m = 0; m < Mm; m++) mx = fmaxf(mx, B1[r*Mm*Gg + m*Gg + g]);
        float e[Mm]; float s = 0.f;
        #pragma unroll
        for (int m = 0; m < Mm; m++) { e[m] = expf(B1[r*Mm*Gg + m*Gg + g] - mx); s += e[m]; }
        float inv = 1.f / s;
        #pragma unroll
        for (int m = 0; m < Mm; m++) g_smB1[r*Mm*Gg + m*Gg + g] = e[m] * inv;
    }
    // Q column (l=r, g): softmax over i (dim 0)
    {
        float mx = -1e30f;
        #pragma unroll
        for (int i = 0; i < Cc; i++) mx = fmaxf(mx, Q[i*Cc*Gg + r*Gg + g]);
        float e[Cc]; float s = 0.f;
        #pragma unroll
        for (int i = 0; i < Cc; i++) { e[i] = expf(Q[i*Cc*Gg + r*Gg + g] - mx); s += e[i]; }
        float inv = 1.f / s;
        #pragma unroll
        for (int i = 0; i < Cc; i++) g_smQ[i*Cc*Gg + r*Gg + g] = e[i] * inv;
    }
    // Pi column g (threads 0..7): softmax over c
    if (t < Gg) {
        float mx = -1e30f;
        #pragma unroll
        for (int c = 0; c < Cc; c++) mx = fmaxf(mx, Pi[c*Gg + t]);
        float e[Cc]; float s = 0.f;
        #pragma unroll
        for (int c = 0; c < Cc; c++) { e[c] = expf(Pi[c*Gg + t] - mx); s += e[c]; }
        float inv = 1.f / s;
        #pragma unroll
        for (int c = 0; c < Cc; c++) g_smPi[c*Gg + t] = e[c] * inv;
    }
}

// ---------------------------------------------------------------------------
// 2) Layer 0: per (n,g) compute post0 and ll0.
// ---------------------------------------------------------------------------
__global__ void k_layer0(const int* __restrict__ x, float* __restrict__ out)
{
    int idx = blockIdx.x * blockDim.x + threadIdx.x;
    if (idx >= Nn * Gg) return;
    int n = idx >> 3, g = idx & 7;
    int xm = x[n];
    float u[Cc]; float s = 0.f;
    #pragma unroll
    for (int c = 0; c < Cc; c++) {
        u[c] = g_smPi[c*Gg + g] * g_smB0[c*Mm*Gg + xm*Gg + g];
        s += u[c];
    }
    out[(size_t)n * (2*Gg) + g] = logf(s);   // ll layer 0
    float inv = 1.f / s;
    size_t base = (size_t)n * CG + g;
    #pragma unroll
    for (int c = 0; c < Cc; c++) g_post0[base + c*Gg] = u[c] * inv;
}

// ---------------------------------------------------------------------------
// 3) Zero the accumulators, vectorized float4. 1.6M float4 stores.
//    grid*block = Nn*CG/4 exactly; first Nn threads also zero cnt.
// ---------------------------------------------------------------------------
__global__ void k_zero()
{
    int i = blockIdx.x * blockDim.x + threadIdx.x;   // < 1.6M
    reinterpret_cast<float4*>(g_aggr)[i] = make_float4(0.f, 0.f, 0.f, 0.f);
    if (i < Nn) g_cnt[i] = 0.f;
}

// ---------------------------------------------------------------------------
// 4) Scatter-add, one WARP per edge. Each lane owns one float4 (lane*4..+3)
//    of the 128-float [C,G] row: one LDG.128 from post0[dst], one
//    red.global.add.v4.f32 into aggr[src]. Lane 0 also bumps the degree count
//    (folds the old k_cnt pass into this kernel).
// ---------------------------------------------------------------------------
__global__ void k_scatter(const int* __restrict__ ei)
{
    int tid  = blockIdx.x * blockDim.x + threadIdx.x;
    int e    = tid >> 5;          // warp id == edge id (grid sized exactly)
    int lane = tid & 31;

    int src, dst;
    if (lane == 0) {
        src = ei[e];
        dst = ei[En + e];
    }
    src = __shfl_sync(0xffffffffu, src, 0);
    dst = __shfl_sync(0xffffffffu, dst, 0);

    if (lane == 0) atomicAdd(&g_cnt[src], 1.0f);

    const float4 v = *reinterpret_cast<const float4*>(
        g_post0 + (size_t)dst * CG + lane * 4);
    float* p = g_aggr + (size_t)src * CG + lane * 4;

    asm volatile("red.global.add.v4.f32 [%0], {%1, %2, %3, %4};"
                 :: "l"(p), "f"(v.x), "f"(v.y), "f"(v.z), "f"(v.w)
                 : "memory");
}

// ---------------------------------------------------------------------------
// 5) Layer 1: per (n,g).
//    post1[i] = B1[i,x,g] * (sum_l Q[i,l,g]*aggr[l]) / norm ; ll1 = log(norm)
// ---------------------------------------------------------------------------
__global__ void k_layer1(const int* __restrict__ x, float* __restrict__ out)
{
    int idx = blockIdx.x * blockDim.x + threadIdx.x;
    if (idx >= Nn * Gg) return;
    int n = idx >> 3, g = idx & 7;
    int xm = x[n];
    float inv_cnt = 1.f / fmaxf(g_cnt[n], 1.f);

    float a[Cc];
    size_t abase = (size_t)n * CG + g;
    #pragma unroll
    for (int l = 0; l < Cc; l++) a[l] = g_aggr[abase + l*Gg] * inv_cnt;

    float tv[Cc]; float norm = 0.f;
    #pragma unroll
    for (int i = 0; i < Cc; i++) {
        float s = 0.f;
        #pragma unroll
        for (int l = 0; l < Cc; l++) s += g_smQ[i*Cc*Gg + l*Gg + g] * a[l];
        float v = g_smB1[i*Mm*Gg + xm*Gg + g] * s;
        tv[i] = v;
        norm += v;
    }
    out[(size_t)n * (2*Gg) + Gg + g] = logf(norm);   // ll layer 1
    float invn = 1.f / norm;
    float* p1 = out + (size_t)Nn * 2 * Gg;
    size_t pbase = (size_t)n * CG + g;
    #pragma unroll
    for (int i = 0; i < Cc; i++) p1[pbase + i*Gg] = tv[i] * invn;
}

// ---------------------------------------------------------------------------
extern "C" void kernel_launch(void* const* d_in, const int* in_sizes, int n_in,
                              void* d_out, int out_size)
{
    const int*   x  = (const int*)  d_in[0];
    const int*   ei = (const int*)  d_in[1];   // [2, E]
    const float* B0 = (const float*)d_in[2];
    const float* Pi = (const float*)d_in[3];
    const float* B1 = (const float*)d_in[4];
    const float* Q  = (const float*)d_in[5];
    float* out = (float*)d_out;

    k_softmax<<<1, 128>>>(B0, Pi, B1, Q);
    k_zero<<<(Nn * CG / 4) / 256, 256>>>();             // 6250 blocks, exact
    k_layer0<<<(Nn * Gg + 255) / 256, 256>>>(x, out);
    k_scatter<<<(En * 32) / 256, 256>>>(ei);            // 100000 blocks, exact
    k_layer1<<<(Nn * Gg + 255) / 256, 256>>>(x, out);
}

// round 6
// speedup vs baseline: 2.8275x; 1.2094x over previous
#include <cuda_runtime.h>
#include <math.h>

#define Nn 50000
#define En 800000
#define Cc 16
#define Mm 32
#define Gg 8
#define CG (Cc*Gg)          // 128

// ---- scratch (module-static, allowed) ----
__device__ float g_smB0[Cc*Mm*Gg];   // softmax(B0, axis=M)
__device__ float g_smPi[Cc*Gg];      // softmax(Pi, axis=C)
__device__ float g_smB1[Cc*Mm*Gg];   // softmax(B1, axis=M)
__device__ float g_smQ[Cc*Cc*Gg];    // softmax(Q, axis=0 (i))
__device__ float g_post0[(size_t)Nn*CG];
__device__ float g_aggr[(size_t)Nn*CG];
__device__ float g_cnt[Nn];

// ---------------------------------------------------------------------------
// 1) All four softmaxes in one small block (128 threads).
// ---------------------------------------------------------------------------
__global__ void k_softmax(const float* __restrict__ B0, const float* __restrict__ Pi,
                          const float* __restrict__ B1, const float* __restrict__ Q)
{
    int t = threadIdx.x;
    if (t >= 128) return;
    int g = t & 7;
    int r = t >> 3;

    // B0 row (c=r, g): softmax over m
    {
        float mx = -1e30f;
        #pragma unroll
        for (int m = 0; m < Mm; m++) mx = fmaxf(mx, B0[r*Mm*Gg + m*Gg + g]);
        float e[Mm]; float s = 0.f;
        #pragma unroll
        for (int m = 0; m < Mm; m++) { e[m] = expf(B0[r*Mm*Gg + m*Gg + g] - mx); s += e[m]; }
        float inv = 1.f / s;
        #pragma unroll
        for (int m = 0; m < Mm; m++) g_smB0[r*Mm*Gg + m*Gg + g] = e[m] * inv;
    }
    // B1 row (c=r, g)
    {
        float mx = -1e30f;
        #pragma unroll
        for (int m = 0; m < Mm; m++) mx = fmaxf(mx, B1[r*Mm*Gg + m*Gg + g]);
        float e[Mm]; float s = 0.f;
        #pragma unroll
        for (int m = 0; m < Mm; m++) { e[m] = expf(B1[r*Mm*Gg + m*Gg + g] - mx); s += e[m]; }
        float inv = 1.f / s;
        #pragma unroll
        for (int m = 0; m < Mm; m++) g_smB1[r*Mm*Gg + m*Gg + g] = e[m] * inv;
    }
    // Q column (l=r, g): softmax over i (dim 0)
    {
        float mx = -1e30f;
        #pragma unroll
        for (int i = 0; i < Cc; i++) mx = fmaxf(mx, Q[i*Cc*Gg + r*Gg + g]);
        float e[Cc]; float s = 0.f;
        #pragma unroll
        for (int i = 0; i < Cc; i++) { e[i] = expf(Q[i*Cc*Gg + r*Gg + g] - mx); s += e[i]; }
        float inv = 1.f / s;
        #pragma unroll
        for (int i = 0; i < Cc; i++) g_smQ[i*Cc*Gg + r*Gg + g] = e[i] * inv;
    }
    // Pi column g (threads 0..7): softmax over c
    if (t < Gg) {
        float mx = -1e30f;
        #pragma unroll
        for (int c = 0; c < Cc; c++) mx = fmaxf(mx, Pi[c*Gg + t]);
        float e[Cc]; float s = 0.f;
        #pragma unroll
        for (int c = 0; c < Cc; c++) { e[c] = expf(Pi[c*Gg + t] - mx); s += e[c]; }
        float inv = 1.f / s;
        #pragma unroll
        for (int c = 0; c < Cc; c++) g_smPi[c*Gg + t] = e[c] * inv;
    }
}

// ---------------------------------------------------------------------------
// 2) Layer 0 + accumulator zeroing fused: per (n,g) compute post0 and ll0,
//    and store zeros to aggr over the same [N,C,G] index space (cnt at g==0).
// ---------------------------------------------------------------------------
__global__ void k_layer0(const int* __restrict__ x, float* __restrict__ out)
{
    int idx = blockIdx.x * blockDim.x + threadIdx.x;
    if (idx >= Nn * Gg) return;
    int n = idx >> 3, g = idx & 7;
    int xm = x[n];
    float u[Cc]; float s = 0.f;
    #pragma unroll
    for (int c = 0; c < Cc; c++) {
        u[c] = g_smPi[c*Gg + g] * g_smB0[c*Mm*Gg + xm*Gg + g];
        s += u[c];
    }
    out[(size_t)n * (2*Gg) + g] = logf(s);   // ll layer 0
    float inv = 1.f / s;
    size_t base = (size_t)n * CG + g;
    #pragma unroll
    for (int c = 0; c < Cc; c++) {
        g_post0[base + c*Gg] = u[c] * inv;
        g_aggr [base + c*Gg] = 0.f;
    }
    if (g == 0) g_cnt[n] = 0.f;
}

// ---------------------------------------------------------------------------
// 3) Scatter-add, one WARP per FOUR edges. Per edge: lane owns one float4
//    (lane*4..+3) of the 128-float [C,G] row -> one LDG.128 + one
//    red.global.add.v4.f32. The 4 LDGs issue back-to-back (MLP=4) before
//    any RED. src/dst come from two broadcast int4 loads (no shfl).
//    Lane 0 bumps the 4 degree counts.
// ---------------------------------------------------------------------------
__global__ void k_scatter(const int* __restrict__ ei)
{
    int wid  = (blockIdx.x * blockDim.x + threadIdx.x) >> 5;  // warp id
    int lane = threadIdx.x & 31;
    int e0   = wid * 4;                                       // grid sized exactly

    const int4 S = *reinterpret_cast<const int4*>(ei + e0);        // 4 src
    const int4 D = *reinterpret_cast<const int4*>(ei + En + e0);   // 4 dst

    if (lane == 0) {
        atomicAdd(&g_cnt[S.x], 1.0f);
        atomicAdd(&g_cnt[S.y], 1.0f);
        atomicAdd(&g_cnt[S.z], 1.0f);
        atomicAdd(&g_cnt[S.w], 1.0f);
    }

    const int off = lane * 4;
    const float4 v0 = *reinterpret_cast<const float4*>(g_post0 + (size_t)D.x * CG + off);
    const float4 v1 = *reinterpret_cast<const float4*>(g_post0 + (size_t)D.y * CG + off);
    const float4 v2 = *reinterpret_cast<const float4*>(g_post0 + (size_t)D.z * CG + off);
    const float4 v3 = *reinterpret_cast<const float4*>(g_post0 + (size_t)D.w * CG + off);

    float* p0 = g_aggr + (size_t)S.x * CG + off;
    float* p1 = g_aggr + (size_t)S.y * CG + off;
    float* p2 = g_aggr + (size_t)S.z * CG + off;
    float* p3 = g_aggr + (size_t)S.w * CG + off;

    asm volatile("red.global.add.v4.f32 [%0], {%1, %2, %3, %4};"
                 :: "l"(p0), "f"(v0.x), "f"(v0.y), "f"(v0.z), "f"(v0.w) : "memory");
    asm volatile("red.global.add.v4.f32 [%0], {%1, %2, %3, %4};"
                 :: "l"(p1), "f"(v1.x), "f"(v1.y), "f"(v1.z), "f"(v1.w) : "memory");
    asm volatile("red.global.add.v4.f32 [%0], {%1, %2, %3, %4};"
                 :: "l"(p2), "f"(v2.x), "f"(v2.y), "f"(v2.z), "f"(v2.w) : "memory");
    asm volatile("red.global.add.v4.f32 [%0], {%1, %2, %3, %4};"
                 :: "l"(p3), "f"(v3.x), "f"(v3.y), "f"(v3.z), "f"(v3.w) : "memory");
}

// ---------------------------------------------------------------------------
// 4) Layer 1: per (n,g).
//    post1[i] = B1[i,x,g] * (sum_l Q[i,l,g]*aggr[l]) / norm ; ll1 = log(norm)
// ---------------------------------------------------------------------------
__global__ void k_layer1(const int* __restrict__ x, float* __restrict__ out)
{
    int idx = blockIdx.x * blockDim.x + threadIdx.x;
    if (idx >= Nn * Gg) return;
    int n = idx >> 3, g = idx & 7;
    int xm = x[n];
    float inv_cnt = 1.f / fmaxf(g_cnt[n], 1.f);

    float a[Cc];
    size_t abase = (size_t)n * CG + g;
    #pragma unroll
    for (int l = 0; l < Cc; l++) a[l] = g_aggr[abase + l*Gg] * inv_cnt;

    float tv[Cc]; float norm = 0.f;
    #pragma unroll
    for (int i = 0; i < Cc; i++) {
        float s = 0.f;
        #pragma unroll
        for (int l = 0; l < Cc; l++) s += g_smQ[i*Cc*Gg + l*Gg + g] * a[l];
        float v = g_smB1[i*Mm*Gg + xm*Gg + g] * s;
        tv[i] = v;
        norm += v;
    }
    out[(size_t)n * (2*Gg) + Gg + g] = logf(norm);   // ll layer 1
    float invn = 1.f / norm;
    float* p1 = out + (size_t)Nn * 2 * Gg;
    size_t pbase = (size_t)n * CG + g;
    #pragma unroll
    for (int i = 0; i < Cc; i++) p1[pbase + i*Gg] = tv[i] * invn;
}

// ---------------------------------------------------------------------------
extern "C" void kernel_launch(void* const* d_in, const int* in_sizes, int n_in,
                              void* d_out, int out_size)
{
    const int*   x  = (const int*)  d_in[0];
    const int*   ei = (const int*)  d_in[1];   // [2, E]
    const float* B0 = (const float*)d_in[2];
    const float* Pi = (const float*)d_in[3];
    const float* B1 = (const float*)d_in[4];
    const float* Q  = (const float*)d_in[5];
    float* out = (float*)d_out;

    k_softmax<<<1, 128>>>(B0, Pi, B1, Q);
    k_layer0<<<(Nn * Gg + 255) / 256, 256>>>(x, out);   // also zeroes aggr/cnt
    k_scatter<<<(En / 4 * 32) / 256, 256>>>(ei);        // 25000 blocks, exact
    k_layer1<<<(Nn * Gg + 255) / 256, 256>>>(x, out);
}